// round 1
// baseline (speedup 1.0000x reference)
#include <cuda_runtime.h>
#include <cuda_bf16.h>
#include <cstdint>
#include <cstddef>

// Problem dims (fixed by reference)
#define Tt 4
#define Bb 16
#define CC 256
#define NN 512
#define HH 1024
#define NHEADS 16
#define DD 16
#define NBATCH (Tt*Bb)   // 64

// ---------------- scratch (static device globals; no allocation) -----------
__device__ float g_bufA[(size_t)NBATCH*CC*NN];   // 33.5 MB
__device__ float g_bufB[(size_t)NBATCH*CC*NN];
__device__ float g_bufC[(size_t)NBATCH*CC*NN];
__device__ float g_bufR[(size_t)NBATCH*CC*NN];
__device__ float g_bufH[(size_t)NBATCH*HH*NN];   // 134 MB

// ---------------- batched GEMM:  Y[b] = W(MxK) * X[b](KxNN) + bias ---------
// grid: (NN/128, M/128, NBATCH), block: 256 threads, 8x8 per thread
__global__ void gemm_kernel(const float* __restrict__ W,
                            const float* __restrict__ X,
                            float* __restrict__ Y,
                            const float* __restrict__ bias,
                            int M, int K)
{
    constexpr int BM = 128, BN = 128, BK = 16, TM = 8, TN = 8;
    __shared__ float As[BK][BM];
    __shared__ float Bs[BK][BN];

    const int batch   = blockIdx.z;
    const float* Xb   = X + (size_t)batch * K * NN;
    float*       Yb   = Y + (size_t)batch * M * NN;
    const int tid     = threadIdx.x;
    const int tr      = tid / (BN / TN);   // 0..15
    const int tc      = tid % (BN / TN);   // 0..15
    const int rowBase = blockIdx.y * BM;
    const int colBase = blockIdx.x * BN;

    float acc[TM][TN];
#pragma unroll
    for (int m = 0; m < TM; m++)
#pragma unroll
        for (int n = 0; n < TN; n++) acc[m][n] = 0.f;

    for (int k0 = 0; k0 < K; k0 += BK) {
        // load W tile (BM x BK) transposed into As[BK][BM]
#pragma unroll
        for (int l = tid; l < BM * BK; l += 256) {
            int i = l >> 4;        // row within tile (BK=16)
            int j = l & 15;        // k within tile
            As[j][i] = W[(size_t)(rowBase + i) * K + (k0 + j)];
        }
        // load X tile (BK x BN) into Bs
#pragma unroll
        for (int l = tid; l < BK * BN; l += 256) {
            int i = l >> 7;        // k within tile (BN=128)
            int j = l & 127;       // col within tile
            Bs[i][j] = Xb[(size_t)(k0 + i) * NN + (colBase + j)];
        }
        __syncthreads();

#pragma unroll
        for (int kk = 0; kk < BK; kk++) {
            float4 a0 = *reinterpret_cast<const float4*>(&As[kk][tr * TM]);
            float4 a1 = *reinterpret_cast<const float4*>(&As[kk][tr * TM + 4]);
            float4 b0 = *reinterpret_cast<const float4*>(&Bs[kk][tc * TN]);
            float4 b1 = *reinterpret_cast<const float4*>(&Bs[kk][tc * TN + 4]);
            float a[TM] = {a0.x, a0.y, a0.z, a0.w, a1.x, a1.y, a1.z, a1.w};
            float b[TN] = {b0.x, b0.y, b0.z, b0.w, b1.x, b1.y, b1.z, b1.w};
#pragma unroll
            for (int m = 0; m < TM; m++)
#pragma unroll
                for (int n = 0; n < TN; n++)
                    acc[m][n] += a[m] * b[n];
        }
        __syncthreads();
    }

#pragma unroll
    for (int m = 0; m < TM; m++) {
        int row = rowBase + tr * TM + m;
        float bi = bias ? bias[row] : 0.f;
        float* yrow = &Yb[(size_t)row * NN + colBase + tc * TN];
#pragma unroll
        for (int n = 0; n < TN; n++) yrow[n] = acc[m][n] + bi;
    }
}

// ---------------- fused BatchNorm (inference affine) + LIF over T ----------
// y layout: (T, B, C, N); one thread per (b,c,n), loops t.
// useBN==0 -> identity affine (attn_lif).
__global__ void bn_lif_kernel(float* __restrict__ y,
                              const float* __restrict__ bn,
                              int C, int useBN)
{
    const size_t plane = (size_t)Bb * C * NN;
    size_t idx = (size_t)blockIdx.x * blockDim.x + threadIdx.x;
    if (idx >= plane) return;
    int c = (int)((idx / NN) % C);

    float scale = 1.f, shift = 0.f;
    if (useBN) {
        float g  = bn[c];
        float be = bn[C + c];
        float mu = bn[2 * C + c];
        float vr = bn[3 * C + c];
        scale = g * rsqrtf(vr + 1e-5f);
        shift = be - mu * scale;
    }

    float mem = 0.f;
#pragma unroll
    for (int t = 0; t < Tt; t++) {
        float v = y[(size_t)t * plane + idx] * scale + shift;
        mem = 0.5f * (mem + v);            // mem += (v-mem)/TAU, TAU=2
        float s = (mem > 0.5f) ? 1.f : 0.f; // spike(mem - THR)
        y[(size_t)t * plane + idx] = s;
        mem -= mem * s;                     // hard reset
    }
}

// ---------------- attention (associative, no softmax) ----------------------
// r = q @ (k^T v) * SCALE^2 ; q,k,v binary spikes in (T,B,C,N), C = H*D.
// One block per (t*B+b, h). Exact: S is integer counts, r = int * 0.0625.
__global__ void attn_kernel(const float* __restrict__ q,
                            const float* __restrict__ k,
                            const float* __restrict__ v,
                            float* __restrict__ r)
{
    constexpr int PAD = 8;
    __shared__ __nv_bfloat16 ks[DD][NN + PAD];
    __shared__ __nv_bfloat16 vs[DD][NN + PAD];
    __shared__ float S[DD][DD];

    const int blk = blockIdx.x;
    const int h   = blk % NHEADS;
    const int tb  = blk / NHEADS;
    const size_t base = (size_t)tb * CC * NN + (size_t)(h * DD) * NN;
    const int tid = threadIdx.x;   // 256

    // stage k, v rows (spikes are exactly representable in bf16)
    for (int i = tid; i < DD * NN; i += 256) {
        int d = i >> 9;      // /512
        int n = i & (NN - 1);
        ks[d][n] = __float2bfloat16(k[base + (size_t)d * NN + n]);
        vs[d][n] = __float2bfloat16(v[base + (size_t)d * NN + n]);
    }
    __syncthreads();

    // S[d1][d2] = sum_m k[m,d1]*v[m,d2]   (integer, exact in fp32)
    {
        int d1 = tid >> 4, d2 = tid & 15;
        float s = 0.f;
#pragma unroll 8
        for (int m = 0; m < NN; m++)
            s += __bfloat162float(ks[d1][m]) * __bfloat162float(vs[d2][m]);
        S[d1][d2] = s;
    }
    __syncthreads();

    // r[.., h*D+d2, n] = (sum_d1 q[d1,n]*S[d1][d2]) * 0.0625
    for (int n = tid; n < NN; n += 256) {
        float qv[DD];
#pragma unroll
        for (int d1 = 0; d1 < DD; d1++)
            qv[d1] = q[base + (size_t)d1 * NN + n];
#pragma unroll
        for (int d2 = 0; d2 < DD; d2++) {
            float acc = 0.f;
#pragma unroll
            for (int d1 = 0; d1 < DD; d1++) acc += qv[d1] * S[d1][d2];
            r[base + (size_t)d2 * NN + n] = acc * 0.0625f;  // SCALE*SCALE
        }
    }
}

// ---------------- elementwise residual add ---------------------------------
__global__ void add_kernel(const float* __restrict__ a,
                           const float* __restrict__ b,
                           float* __restrict__ o, size_t n4)
{
    size_t i = (size_t)blockIdx.x * blockDim.x + threadIdx.x;
    if (i >= n4) return;
    float4 av = reinterpret_cast<const float4*>(a)[i];
    float4 bv = reinterpret_cast<const float4*>(b)[i];
    float4 ov;
    ov.x = av.x + bv.x; ov.y = av.y + bv.y;
    ov.z = av.z + bv.z; ov.w = av.w + bv.w;
    reinterpret_cast<float4*>(o)[i] = ov;
}

// ---------------------------------------------------------------------------
extern "C" void kernel_launch(void* const* d_in, const int* in_sizes, int n_in,
                              void* d_out, int out_size)
{
    const float* x       = (const float*)d_in[0];
    const float* q_w     = (const float*)d_in[1];
    const float* q_bn    = (const float*)d_in[2];
    const float* k_w     = (const float*)d_in[3];
    const float* k_bn    = (const float*)d_in[4];
    const float* v_w     = (const float*)d_in[5];
    const float* v_bn    = (const float*)d_in[6];
    const float* proj_w  = (const float*)d_in[7];
    const float* proj_bn = (const float*)d_in[8];
    const float* fc1_w   = (const float*)d_in[9];
    const float* fc1_b   = (const float*)d_in[10];
    const float* fc1_bn  = (const float*)d_in[11];
    const float* fc2_w   = (const float*)d_in[12];
    const float* fc2_b   = (const float*)d_in[13];
    const float* fc2_bn  = (const float*)d_in[14];
    float* out = (float*)d_out;

    float *bufA, *bufB, *bufC, *bufR, *bufH;
    cudaGetSymbolAddress((void**)&bufA, g_bufA);
    cudaGetSymbolAddress((void**)&bufB, g_bufB);
    cudaGetSymbolAddress((void**)&bufC, g_bufC);
    cudaGetSymbolAddress((void**)&bufR, g_bufR);
    cudaGetSymbolAddress((void**)&bufH, g_bufH);

    const dim3 blk(256);
    const dim3 gconv(NN / 128, CC / 128, NBATCH);   // (4, 2, 64)
    const dim3 gfc1 (NN / 128, HH / 128, NBATCH);   // (4, 8, 64)

    const size_t planeC = (size_t)Bb * CC * NN;     // 2,097,152
    const size_t planeH = (size_t)Bb * HH * NN;     // 8,388,608
    const int gridLifC  = (int)((planeC + 255) / 256);
    const int gridLifH  = (int)((planeH + 255) / 256);
    const size_t total  = (size_t)Tt * planeC;      // 8,388,608
    const int gridAdd   = (int)((total / 4 + 255) / 256);

    // Q / K / V : conv (1x1) -> BN -> LIF
    gemm_kernel<<<gconv, blk>>>(q_w, x, bufA, nullptr, CC, CC);
    bn_lif_kernel<<<gridLifC, 256>>>(bufA, q_bn, CC, 1);
    gemm_kernel<<<gconv, blk>>>(k_w, x, bufB, nullptr, CC, CC);
    bn_lif_kernel<<<gridLifC, 256>>>(bufB, k_bn, CC, 1);
    gemm_kernel<<<gconv, blk>>>(v_w, x, bufC, nullptr, CC, CC);
    bn_lif_kernel<<<gridLifC, 256>>>(bufC, v_bn, CC, 1);

    // attention (associative): r = q @ (k^T v) * SCALE^2, then attn_lif (no BN)
    attn_kernel<<<NBATCH * NHEADS, 256>>>(bufA, bufB, bufC, bufR);
    bn_lif_kernel<<<gridLifC, 256>>>(bufR, nullptr, CC, 0);

    // proj conv -> BN -> LIF, residual 1
    gemm_kernel<<<gconv, blk>>>(proj_w, bufR, bufA, nullptr, CC, CC);
    bn_lif_kernel<<<gridLifC, 256>>>(bufA, proj_bn, CC, 1);
    add_kernel<<<gridAdd, 256>>>(x, bufA, bufB, total / 4);   // bufB = x2

    // MLP: fc1 -> BN -> LIF, fc2 -> BN -> LIF, residual 2
    gemm_kernel<<<gfc1, blk>>>(fc1_w, bufB, bufH, fc1_b, HH, CC);
    bn_lif_kernel<<<gridLifH, 256>>>(bufH, fc1_bn, HH, 1);
    gemm_kernel<<<gconv, blk>>>(fc2_w, bufH, bufC, fc2_b, CC, HH);
    bn_lif_kernel<<<gridLifC, 256>>>(bufC, fc2_bn, CC, 1);
    add_kernel<<<gridAdd, 256>>>(bufB, bufC, out, total / 4);
}

// round 4
// speedup vs baseline: 2.5032x; 2.5032x over previous
#include <cuda_runtime.h>
#include <cuda_bf16.h>
#include <cstdint>
#include <cstddef>

// Problem dims (fixed by reference)
#define Tt 4
#define Bb 16
#define CC 256
#define NN 512
#define HH 1024
#define NHEADS 16
#define DD 16
#define NBATCH (Tt*Bb)   // 64

#define PLANE_C ((size_t)NBATCH*CC*NN)   // 8,388,608
#define PLANE_H ((size_t)NBATCH*HH*NN)   // 33,554,432

// ---------------- scratch (static device globals; no allocation) -----------
// weight splits: [3][M][K] per weight, concatenated
#define OFF_Q  0
#define OFF_K  (3*256*256)
#define OFF_V  (2*3*256*256)
#define OFF_P  (3*3*256*256)
#define OFF_F1 (4*3*256*256)
#define OFF_F2 (4*3*256*256 + 3*1024*256)
__device__ __nv_bfloat16 g_wsplit[4*3*256*256 + 2*3*1024*256];

__device__ __nv_bfloat16 g_bsplit[3*PLANE_C];   // 3-term split of x / x2
__device__ __nv_bfloat16 g_q[PLANE_C];          // spike planes (bf16 exact)
__device__ __nv_bfloat16 g_k[PLANE_C];
__device__ __nv_bfloat16 g_v[PLANE_C];
__device__ __nv_bfloat16 g_s[PLANE_C];          // attn_lif / fc2 spikes
__device__ __nv_bfloat16 g_s2[PLANE_C];         // proj spikes
__device__ __nv_bfloat16 g_hs[PLANE_H];         // fc1 spikes
__device__ float g_f[PLANE_C];                  // fp32 GEMM out (C-sized)
__device__ float g_h[PLANE_H];                  // fp32 GEMM out (H-sized)
__device__ float g_x2[PLANE_C];                 // residual-1 result

// ---------------- helpers ---------------------------------------------------
__device__ __forceinline__ void cpasync16(void* smem_dst, const void* gsrc) {
    uint32_t s = (uint32_t)__cvta_generic_to_shared(smem_dst);
    asm volatile("cp.async.cg.shared.global [%0], [%1], 16;" :: "r"(s), "l"(gsrc));
}
__device__ __forceinline__ void ldm_x4(uint32_t* r, uint32_t addr) {
    asm volatile("ldmatrix.sync.aligned.m8n8.x4.shared.b16 {%0,%1,%2,%3}, [%4];"
                 : "=r"(r[0]), "=r"(r[1]), "=r"(r[2]), "=r"(r[3]) : "r"(addr));
}
__device__ __forceinline__ void ldm_x4_t(uint32_t* r, uint32_t addr) {
    asm volatile("ldmatrix.sync.aligned.m8n8.x4.trans.shared.b16 {%0,%1,%2,%3}, [%4];"
                 : "=r"(r[0]), "=r"(r[1]), "=r"(r[2]), "=r"(r[3]) : "r"(addr));
}
__device__ __forceinline__ void mma16816(float* c, const uint32_t* a, const uint32_t* b) {
    asm volatile("mma.sync.aligned.m16n8k16.row.col.f32.bf16.bf16.f32 "
                 "{%0,%1,%2,%3}, {%4,%5,%6,%7}, {%8,%9}, {%0,%1,%2,%3};"
                 : "+f"(c[0]), "+f"(c[1]), "+f"(c[2]), "+f"(c[3])
                 : "r"(a[0]), "r"(a[1]), "r"(a[2]), "r"(a[3]), "r"(b[0]), "r"(b[1]));
}

// ---------------- split-precision bf16 tensor-core GEMM ---------------------
// Y[batch] = sum_pairs A_i (MxK) * B_j (KxNN), fp32 out (+bias)
// Pairs ordered SMALLEST magnitude first so the h*h pair accumulates last
// at full magnitude (matches reference fp32 rounding budget).
// mode 0: 6 pairs (general fp32 operands); mode 1: 3 pairs (B exact spikes)
__global__ __launch_bounds__(256) void gemm_mma(
    const __nv_bfloat16* __restrict__ A,   // [3][M][K]
    const __nv_bfloat16* __restrict__ B,   // [term][batch][K][NN]
    float* __restrict__ Y,                 // [batch][M][NN]
    const float* __restrict__ bias,
    int M, int K, size_t termStrideB, int mode)
{
    constexpr int BM = 128, BN = 128, BK = 32;
    __shared__ __nv_bfloat16 As[2][BM][BK + 8];
    __shared__ __nv_bfloat16 Bs[2][BK][BN + 8];

    int pa[6], pb[6], np;
    if (mode == 0) {
        np = 6;   // ascending magnitude: 2^-18, 2^-18, 2^-18, 2^-9, 2^-9, 1
        pa[0]=2; pa[1]=1; pa[2]=0; pa[3]=1; pa[4]=0; pa[5]=0;
        pb[0]=0; pb[1]=1; pb[2]=2; pb[3]=0; pb[4]=1; pb[5]=0;
    } else {
        np = 3;   // ascending: w_l*s, w_m*s, w_h*s
        pa[0]=2; pa[1]=1; pa[2]=0;
        pb[0]=0; pb[1]=0; pb[2]=0;
    }

    const int tid  = threadIdx.x;
    const int wid  = tid >> 5, lane = tid & 31;
    const int wm   = (wid >> 2) * 64;      // warp m offset within BM
    const int wn   = (wid & 3) * 32;       // warp n offset within BN
    const int batch = blockIdx.z;
    const int m0 = blockIdx.y * BM, n0 = blockIdx.x * BN;
    const size_t Bbase = (size_t)batch * K * NN;

    float acc[4][4][4];
#pragma unroll
    for (int i = 0; i < 4; i++)
#pragma unroll
        for (int j = 0; j < 4; j++)
#pragma unroll
            for (int l = 0; l < 4; l++) acc[i][j][l] = 0.f;

    const int kTiles = K / BK;
    const int nIter  = np * kTiles;

    auto loadStage = [&](int it, int s) {
        int p  = it / kTiles;
        int kk = (it % kTiles) * BK;
        const __nv_bfloat16* Ap = A + (size_t)pa[p] * M * K + (size_t)m0 * K + kk;
        const __nv_bfloat16* Bp = B + (size_t)pb[p] * termStrideB + Bbase
                                    + (size_t)kk * NN + n0;
#pragma unroll
        for (int i = 0; i < 2; i++) {                 // A: 128 rows x 64B
            int c = tid + 256 * i;
            int r = c >> 2, sg = (c & 3) * 8;
            cpasync16(&As[s][r][sg], Ap + (size_t)r * K + sg);
        }
#pragma unroll
        for (int i = 0; i < 2; i++) {                 // B: 32 rows x 256B
            int c = tid + 256 * i;
            int r = c >> 4, sg = (c & 15) * 8;
            cpasync16(&Bs[s][r][sg], Bp + (size_t)r * NN + sg);
        }
        asm volatile("cp.async.commit_group;");
    };

    loadStage(0, 0);
    for (int it = 0; it < nIter; it++) {
        int s = it & 1;
        if (it + 1 < nIter) {
            loadStage(it + 1, s ^ 1);
            asm volatile("cp.async.wait_group 1;");
        } else {
            asm volatile("cp.async.wait_group 0;");
        }
        __syncthreads();

#pragma unroll
        for (int ks = 0; ks < BK; ks += 16) {
            uint32_t af[4][4];
            uint32_t bf[4][2];
#pragma unroll
            for (int mf = 0; mf < 4; mf++) {
                uint32_t addr = (uint32_t)__cvta_generic_to_shared(
                    &As[s][wm + mf * 16 + (lane & 15)][ks + ((lane >> 4) << 3)]);
                ldm_x4(af[mf], addr);
            }
#pragma unroll
            for (int g = 0; g < 2; g++) {
                uint32_t tmp[4];
                uint32_t addr = (uint32_t)__cvta_generic_to_shared(
                    &Bs[s][ks + (lane & 15)][wn + g * 16 + ((lane >> 4) << 3)]);
                ldm_x4_t(tmp, addr);
                bf[2 * g][0]     = tmp[0]; bf[2 * g][1]     = tmp[1];
                bf[2 * g + 1][0] = tmp[2]; bf[2 * g + 1][1] = tmp[3];
            }
#pragma unroll
            for (int mf = 0; mf < 4; mf++)
#pragma unroll
                for (int nf = 0; nf < 4; nf++)
                    mma16816(acc[mf][nf], af[mf], bf[nf]);
        }
        __syncthreads();
    }

    // epilogue
    float* Yb = Y + (size_t)batch * M * NN;
#pragma unroll
    for (int mf = 0; mf < 4; mf++) {
        int mrow = m0 + wm + mf * 16 + (lane >> 2);
        float b0 = bias ? bias[mrow] : 0.f;
        float b1 = bias ? bias[mrow + 8] : 0.f;
#pragma unroll
        for (int nf = 0; nf < 4; nf++) {
            int ncol = n0 + wn + nf * 8 + 2 * (lane & 3);
            float2 v0 = make_float2(__fadd_rn(acc[mf][nf][0], b0),
                                    __fadd_rn(acc[mf][nf][1], b0));
            float2 v1 = make_float2(__fadd_rn(acc[mf][nf][2], b1),
                                    __fadd_rn(acc[mf][nf][3], b1));
            *reinterpret_cast<float2*>(&Yb[(size_t)mrow * NN + ncol])       = v0;
            *reinterpret_cast<float2*>(&Yb[(size_t)(mrow + 8) * NN + ncol]) = v1;
        }
    }
}

// ---------------- fp32 -> 3-term bf16 split ---------------------------------
__global__ void split3_kernel(const float* __restrict__ in,
                              __nv_bfloat16* __restrict__ out,
                              size_t n, size_t stride)
{
    size_t i = (size_t)blockIdx.x * blockDim.x + threadIdx.x;
    if (i >= n) return;
    float v = in[i];
    __nv_bfloat16 h = __float2bfloat16(v);
    float r = __fsub_rn(v, __bfloat162float(h));
    __nv_bfloat16 m = __float2bfloat16(r);
    float r2 = __fsub_rn(r, __bfloat162float(m));
    __nv_bfloat16 l = __float2bfloat16(r2);
    out[i] = h; out[stride + i] = m; out[2 * stride + i] = l;
}

// ---------------- residual add + 3-term split (x2 = x + spikes) -------------
__global__ void addsplit_kernel(const float* __restrict__ x,
                                const __nv_bfloat16* __restrict__ s,
                                float* __restrict__ x2,
                                __nv_bfloat16* __restrict__ out, size_t n)
{
    size_t i = (size_t)blockIdx.x * blockDim.x + threadIdx.x;
    if (i >= n) return;
    float v = __fadd_rn(x[i], __bfloat162float(s[i]));
    x2[i] = v;
    __nv_bfloat16 h = __float2bfloat16(v);
    float r = __fsub_rn(v, __bfloat162float(h));
    __nv_bfloat16 m = __float2bfloat16(r);
    float r2 = __fsub_rn(r, __bfloat162float(m));
    out[i] = h; out[n + i] = m; out[2 * n + i] = __float2bfloat16(r2);
}

// ---------------- BatchNorm (exact reference forms) + LIF over T ------------
// BN: y = (x - mu) * (g / sqrt(var+eps)) + beta, no contraction, no MUFU.
// LIF: mem = mem + (v - mem)*0.5 ; spike at mem>0.5 ; hard reset.
__global__ void bn_lif_kernel(const float* __restrict__ y,
                              __nv_bfloat16* __restrict__ out,
                              const float* __restrict__ bn,
                              int C, int useBN)
{
    const size_t plane = (size_t)Bb * C * NN;
    size_t idx = (size_t)blockIdx.x * blockDim.x + threadIdx.x;
    if (idx >= plane) return;
    int c = (int)((idx / NN) % C);

    float inv = 1.f, mu = 0.f, be = 0.f;
    if (useBN) {
        float g  = bn[c];
        be       = bn[C + c];
        mu       = bn[2 * C + c];
        float vr = bn[3 * C + c];
        inv = __fdiv_rn(g, __fsqrt_rn(__fadd_rn(vr, 1e-5f)));
    }

    float mem = 0.f;
#pragma unroll
    for (int t = 0; t < Tt; t++) {
        float v = y[(size_t)t * plane + idx];
        if (useBN)
            v = __fadd_rn(__fmul_rn(__fsub_rn(v, mu), inv), be);
        float d = __fsub_rn(v, mem);
        mem = __fadd_rn(mem, __fmul_rn(d, 0.5f));     // mem += (v-mem)/TAU
        float s = (mem > 0.5f) ? 1.f : 0.f;
        out[(size_t)t * plane + idx] = __float2bfloat16(s);
        mem = __fmul_rn(mem, __fsub_rn(1.f, s));      // hard reset
    }
}

// ---------------- attention (associative, no softmax), bf16 spikes in -------
// r = q @ (k^T v) * SCALE^2 — exact: integer counts * 0.0625.
__global__ void attn_kernel(const __nv_bfloat16* __restrict__ q,
                            const __nv_bfloat16* __restrict__ k,
                            const __nv_bfloat16* __restrict__ v,
                            float* __restrict__ r)
{
    __shared__ __nv_bfloat16 ks[DD][NN + 8];
    __shared__ __nv_bfloat16 vs[DD][NN + 8];
    __shared__ float S[DD][DD];

    const int blk = blockIdx.x;
    const int h   = blk % NHEADS;
    const int tb  = blk / NHEADS;
    const size_t base = (size_t)tb * CC * NN + (size_t)(h * DD) * NN;
    const int tid = threadIdx.x;   // 256

    for (int i = tid; i < DD * NN; i += 256) {
        int d = i >> 9;
        int n = i & (NN - 1);
        ks[d][n] = k[base + (size_t)d * NN + n];
        vs[d][n] = v[base + (size_t)d * NN + n];
    }
    __syncthreads();

    {   // S[d1][d2] = sum_m k[m,d1]*v[m,d2] (exact integer counts)
        int d1 = tid >> 4, d2 = tid & 15;
        float s = 0.f;
#pragma unroll 8
        for (int m = 0; m < NN; m++)
            s += __bfloat162float(ks[d1][m]) * __bfloat162float(vs[d2][m]);
        S[d1][d2] = s;
    }
    __syncthreads();

    for (int n = tid; n < NN; n += 256) {
        float qv[DD];
#pragma unroll
        for (int d1 = 0; d1 < DD; d1++)
            qv[d1] = __bfloat162float(q[base + (size_t)d1 * NN + n]);
#pragma unroll
        for (int d2 = 0; d2 < DD; d2++) {
            float acc = 0.f;
#pragma unroll
            for (int d1 = 0; d1 < DD; d1++) acc += qv[d1] * S[d1][d2];
            r[base + (size_t)d2 * NN + n] = acc * 0.0625f;  // SCALE*SCALE
        }
    }
}

// ---------------- final residual add ----------------------------------------
__global__ void final_add_kernel(const float* __restrict__ x2,
                                 const __nv_bfloat16* __restrict__ s,
                                 float* __restrict__ o, size_t n)
{
    size_t i = (size_t)blockIdx.x * blockDim.x + threadIdx.x;
    if (i >= n) return;
    o[i] = __fadd_rn(x2[i], __bfloat162float(s[i]));
}

// ---------------------------------------------------------------------------
extern "C" void kernel_launch(void* const* d_in, const int* in_sizes, int n_in,
                              void* d_out, int out_size)
{
    const float* x       = (const float*)d_in[0];
    const float* q_w     = (const float*)d_in[1];
    const float* q_bn    = (const float*)d_in[2];
    const float* k_w     = (const float*)d_in[3];
    const float* k_bn    = (const float*)d_in[4];
    const float* v_w     = (const float*)d_in[5];
    const float* v_bn    = (const float*)d_in[6];
    const float* proj_w  = (const float*)d_in[7];
    const float* proj_bn = (const float*)d_in[8];
    const float* fc1_w   = (const float*)d_in[9];
    const float* fc1_b   = (const float*)d_in[10];
    const float* fc1_bn  = (const float*)d_in[11];
    const float* fc2_w   = (const float*)d_in[12];
    const float* fc2_b   = (const float*)d_in[13];
    const float* fc2_bn  = (const float*)d_in[14];
    float* out = (float*)d_out;

    __nv_bfloat16 *wsp, *bsp, *gq, *gk, *gv, *gs, *gs2, *ghs;
    float *gf, *gh, *gx2;
    cudaGetSymbolAddress((void**)&wsp, g_wsplit);
    cudaGetSymbolAddress((void**)&bsp, g_bsplit);
    cudaGetSymbolAddress((void**)&gq,  g_q);
    cudaGetSymbolAddress((void**)&gk,  g_k);
    cudaGetSymbolAddress((void**)&gv,  g_v);
    cudaGetSymbolAddress((void**)&gs,  g_s);
    cudaGetSymbolAddress((void**)&gs2, g_s2);
    cudaGetSymbolAddress((void**)&ghs, g_hs);
    cudaGetSymbolAddress((void**)&gf,  g_f);
    cudaGetSymbolAddress((void**)&gh,  g_h);
    cudaGetSymbolAddress((void**)&gx2, g_x2);

    const size_t planeC = (size_t)Bb * CC * NN;   // 2,097,152
    const size_t planeH = (size_t)Bb * HH * NN;   // 8,388,608
    const int gLifC = (int)((planeC + 255) / 256);
    const int gLifH = (int)((planeH + 255) / 256);
    const int gEltC = (int)((PLANE_C + 255) / 256);

    // weight splits (tiny)
    split3_kernel<<<256, 256>>>(q_w,    wsp + OFF_Q,  65536, 65536);
    split3_kernel<<<256, 256>>>(k_w,    wsp + OFF_K,  65536, 65536);
    split3_kernel<<<256, 256>>>(v_w,    wsp + OFF_V,  65536, 65536);
    split3_kernel<<<256, 256>>>(proj_w, wsp + OFF_P,  65536, 65536);
    split3_kernel<<<1024, 256>>>(fc1_w, wsp + OFF_F1, 262144, 262144);
    split3_kernel<<<1024, 256>>>(fc2_w, wsp + OFF_F2, 262144, 262144);

    // x splits
    split3_kernel<<<gEltC, 256>>>(x, bsp, PLANE_C, PLANE_C);

    const dim3 gemmC(NN / 128, CC / 128, NBATCH);   // (4, 2, 64)
    const dim3 gemmH(NN / 128, HH / 128, NBATCH);   // (4, 8, 64)

    // Q / K / V : split-GEMM -> BN -> LIF (bf16 spikes)
    gemm_mma<<<gemmC, 256>>>(wsp + OFF_Q, bsp, gf, nullptr, CC, CC, PLANE_C, 0);
    bn_lif_kernel<<<gLifC, 256>>>(gf, gq, q_bn, CC, 1);
    gemm_mma<<<gemmC, 256>>>(wsp + OFF_K, bsp, gf, nullptr, CC, CC, PLANE_C, 0);
    bn_lif_kernel<<<gLifC, 256>>>(gf, gk, k_bn, CC, 1);
    gemm_mma<<<gemmC, 256>>>(wsp + OFF_V, bsp, gf, nullptr, CC, CC, PLANE_C, 0);
    bn_lif_kernel<<<gLifC, 256>>>(gf, gv, v_bn, CC, 1);

    // attention (associative) + attn_lif
    attn_kernel<<<NBATCH * NHEADS, 256>>>(gq, gk, gv, gf);
    bn_lif_kernel<<<gLifC, 256>>>(gf, gs, nullptr, CC, 0);

    // proj (spike input: 3 exact products) -> BN -> LIF, residual 1 + resplit
    gemm_mma<<<gemmC, 256>>>(wsp + OFF_P, gs, gf, nullptr, CC, CC, 0, 1);
    bn_lif_kernel<<<gLifC, 256>>>(gf, gs2, proj_bn, CC, 1);
    addsplit_kernel<<<gEltC, 256>>>(x, gs2, gx2, bsp, PLANE_C);

    // MLP
    gemm_mma<<<gemmH, 256>>>(wsp + OFF_F1, bsp, gh, fc1_b, HH, CC, PLANE_C, 0);
    bn_lif_kernel<<<gLifH, 256>>>(gh, ghs, fc1_bn, HH, 1);
    gemm_mma<<<gemmC, 256>>>(wsp + OFF_F2, ghs, gf, fc2_b, CC, HH, 0, 1);
    bn_lif_kernel<<<gLifC, 256>>>(gf, gs, fc2_bn, CC, 1);
    final_add_kernel<<<gEltC, 256>>>(gx2, gs, out, PLANE_C);
}

// round 5
// speedup vs baseline: 2.5601x; 1.0227x over previous
#include <cuda_runtime.h>
#include <cuda_bf16.h>
#include <cstdint>
#include <cstddef>

// Problem dims (fixed by reference)
#define Tt 4
#define Bb 16
#define CC 256
#define NN 512
#define HH 1024
#define NHEADS 16
#define DD 16
#define NBATCH (Tt*Bb)   // 64

#define PLANE_C ((size_t)NBATCH*CC*NN)   // 8,388,608
#define PLANE_H ((size_t)NBATCH*HH*NN)   // 33,554,432

// ---------------- scratch (static device globals; no allocation) -----------
// qkv stacked weight split: [3][768][256]; proj/fc1/fc2: [3][M][K]
#define OFF_QKV 0
#define OFF_P   (3*768*256)
#define OFF_F1  (3*768*256 + 3*256*256)
#define OFF_F2  (3*768*256 + 3*256*256 + 3*1024*256)
__device__ __nv_bfloat16 g_wsplit[3*768*256 + 3*256*256 + 2*3*1024*256];

__device__ __nv_bfloat16 g_bsplit[3*PLANE_C];   // 3-term split of x / x2
__device__ __nv_bfloat16 g_q[PLANE_C];          // spike planes (bf16 exact)
__device__ __nv_bfloat16 g_k[PLANE_C];
__device__ __nv_bfloat16 g_v[PLANE_C];
__device__ __nv_bfloat16 g_s[PLANE_C];          // attn_lif / fc2 spikes
__device__ __nv_bfloat16 g_s2[PLANE_C];         // proj spikes
__device__ __nv_bfloat16 g_hs[PLANE_H];         // fc1 spikes
__device__ float g_f[PLANE_C];                  // fp32 GEMM out (C-sized)
__device__ float g_h[PLANE_H];                  // fp32 GEMM out (H / qkv-stacked)
__device__ float g_x2[PLANE_C];                 // residual-1 result

// ---------------- helpers ---------------------------------------------------
__device__ __forceinline__ void cpasync16(void* smem_dst, const void* gsrc) {
    uint32_t s = (uint32_t)__cvta_generic_to_shared(smem_dst);
    asm volatile("cp.async.cg.shared.global [%0], [%1], 16;" :: "r"(s), "l"(gsrc));
}
__device__ __forceinline__ void ldm_x4(uint32_t* r, uint32_t addr) {
    asm volatile("ldmatrix.sync.aligned.m8n8.x4.shared.b16 {%0,%1,%2,%3}, [%4];"
                 : "=r"(r[0]), "=r"(r[1]), "=r"(r[2]), "=r"(r[3]) : "r"(addr));
}
__device__ __forceinline__ void ldm_x4_t(uint32_t* r, uint32_t addr) {
    asm volatile("ldmatrix.sync.aligned.m8n8.x4.trans.shared.b16 {%0,%1,%2,%3}, [%4];"
                 : "=r"(r[0]), "=r"(r[1]), "=r"(r[2]), "=r"(r[3]) : "r"(addr));
}
__device__ __forceinline__ void mma16816(float* c, const uint32_t* a, const uint32_t* b) {
    asm volatile("mma.sync.aligned.m16n8k16.row.col.f32.bf16.bf16.f32 "
                 "{%0,%1,%2,%3}, {%4,%5,%6,%7}, {%8,%9}, {%0,%1,%2,%3};"
                 : "+f"(c[0]), "+f"(c[1]), "+f"(c[2]), "+f"(c[3])
                 : "r"(a[0]), "r"(a[1]), "r"(a[2]), "r"(a[3]), "r"(b[0]), "r"(b[1]));
}

// smem layout constants (bytes)
#define A_TERM 10240     // 128 rows * 80B (40 bf16, +8 pad)
#define A_STG  (3*A_TERM)
#define B_TERM 8704      // 32 rows * 272B (136 bf16, +8 pad)
#define B_STG  (3*B_TERM)
#define B_OFF  (2*A_STG)
#define SMEM_BYTES (2*A_STG + 2*B_STG)   // 113,664

// ---------------- fused split-precision bf16 tensor-core GEMM ---------------
// Y[batch] = (sum over term-combos) A_i (MxK) * B_j (KxNN) + bias, fp32 out.
// All terms fused into ONE K-pass: per k-tile, load 3 A-term + nb B-term
// tiles, issue all combos. Dual accumulator: accL takes only the h*h combo
// (matches reference fp32 rounding profile); accS takes the corrections in
// ascending magnitude order. mode 0: 6 combos; mode 1 (B exact spikes): 3.
__global__ __launch_bounds__(256) void gemm_mma(
    const __nv_bfloat16* __restrict__ A,   // [3][M][K] (h,m,l terms)
    const __nv_bfloat16* __restrict__ B,   // [term][batch][K][NN]
    float* __restrict__ Y,                 // [batch][M][NN]
    const float* __restrict__ bias,
    int M, int K, size_t termStrideB, int mode)
{
    extern __shared__ __align__(16) char smem[];

    const int tid  = threadIdx.x;
    const int wid  = tid >> 5, lane = tid & 31;
    const int wm   = (wid >> 2) * 64;      // warp m offset within BM=128
    const int wn   = (wid & 3) * 32;       // warp n offset within BN=128
    const int batch = blockIdx.z;
    const int m0 = blockIdx.y * 128, n0 = blockIdx.x * 128;
    const size_t Bbase = (size_t)batch * K * NN;
    const int nb = (mode == 0) ? 3 : 1;

    float accL[4][4][4], accS[4][4][4];
#pragma unroll
    for (int i = 0; i < 4; i++)
#pragma unroll
        for (int j = 0; j < 4; j++)
#pragma unroll
            for (int l = 0; l < 4; l++) { accL[i][j][l] = 0.f; accS[i][j][l] = 0.f; }

    const int kTiles = K / 32;

    auto loadStage = [&](int it, int s) {
        int kk = it * 32;
        // A: 3 terms x 128 rows x 64B
#pragma unroll
        for (int j = 0; j < 6; j++) {
            int c = tid + 256 * j;
            int t = c >> 9, rem = c & 511;
            int r = rem >> 2, sg = (rem & 3) * 8;
            cpasync16(smem + s * A_STG + t * A_TERM + r * 80 + sg * 2,
                      A + (size_t)t * M * K + (size_t)(m0 + r) * K + kk + sg);
        }
        // B: nb terms x 32 rows x 256B
        for (int j = 0; j < 2 * nb; j++) {
            int c = tid + 256 * j;
            int t = c >> 9, rem = c & 511;
            int r = rem >> 4, sg = (rem & 15) * 8;
            cpasync16(smem + B_OFF + s * B_STG + t * B_TERM + r * 272 + sg * 2,
                      B + (size_t)t * termStrideB + Bbase + (size_t)(kk + r) * NN + n0 + sg);
        }
        asm volatile("cp.async.commit_group;");
    };

    auto loadA = [&](uint32_t af[4][4], int t, int s, int ks) {
#pragma unroll
        for (int mf = 0; mf < 4; mf++) {
            const char* p = smem + s * A_STG + t * A_TERM
                          + (wm + mf * 16 + (lane & 15)) * 80
                          + (ks + ((lane >> 4) << 3)) * 2;
            ldm_x4(af[mf], (uint32_t)__cvta_generic_to_shared(p));
        }
    };
    auto loadB = [&](uint32_t bfr[4][2], int t, int s, int ks) {
#pragma unroll
        for (int g = 0; g < 2; g++) {
            const char* p = smem + B_OFF + s * B_STG + t * B_TERM
                          + (ks + (lane & 15)) * 272
                          + (wn + g * 16 + ((lane >> 4) << 3)) * 2;
            uint32_t tmp[4];
            ldm_x4_t(tmp, (uint32_t)__cvta_generic_to_shared(p));
            bfr[2 * g][0]     = tmp[0]; bfr[2 * g][1]     = tmp[1];
            bfr[2 * g + 1][0] = tmp[2]; bfr[2 * g + 1][1] = tmp[3];
        }
    };
    auto mmaAll = [&](float acc[4][4][4], uint32_t af[4][4], uint32_t bfr[4][2]) {
#pragma unroll
        for (int mf = 0; mf < 4; mf++)
#pragma unroll
            for (int nf = 0; nf < 4; nf++)
                mma16816(acc[mf][nf], af[mf], bfr[nf]);
    };

    loadStage(0, 0);
    for (int it = 0; it < kTiles; it++) {
        int s = it & 1;
        if (it + 1 < kTiles) {
            loadStage(it + 1, s ^ 1);
            asm volatile("cp.async.wait_group 1;");
        } else {
            asm volatile("cp.async.wait_group 0;");
        }
        __syncthreads();

#pragma unroll
        for (int ks = 0; ks < 32; ks += 16) {
            uint32_t af[4][4];
            if (mode == 0) {
                uint32_t b0[4][2], b1[4][2], b2[4][2];
                loadB(b0, 0, s, ks); loadB(b1, 1, s, ks); loadB(b2, 2, s, ks);
                // ascending magnitude: (l,h),(m,m),(h,l) | (h,m),(m,h) | (h,h)
                loadA(af, 2, s, ks); mmaAll(accS, af, b0);            // l*h
                loadA(af, 1, s, ks); mmaAll(accS, af, b1);            // m*m
                loadA(af, 0, s, ks); mmaAll(accS, af, b2);            // h*l
                                     mmaAll(accS, af, b1);            // h*m
                loadA(af, 1, s, ks); mmaAll(accS, af, b0);            // m*h
                loadA(af, 0, s, ks); mmaAll(accL, af, b0);            // h*h
            } else {
                uint32_t b0[4][2];
                loadB(b0, 0, s, ks);
                loadA(af, 2, s, ks); mmaAll(accS, af, b0);            // l*s
                loadA(af, 1, s, ks); mmaAll(accS, af, b0);            // m*s
                loadA(af, 0, s, ks); mmaAll(accL, af, b0);            // h*s
            }
        }
        __syncthreads();
    }

    // epilogue: acc = accS + accL (+bias)
    float* Yb = Y + (size_t)batch * M * NN;
#pragma unroll
    for (int mf = 0; mf < 4; mf++) {
        int mrow = m0 + wm + mf * 16 + (lane >> 2);
        float b0 = bias ? bias[mrow] : 0.f;
        float b1 = bias ? bias[mrow + 8] : 0.f;
#pragma unroll
        for (int nf = 0; nf < 4; nf++) {
            int ncol = n0 + wn + nf * 8 + 2 * (lane & 3);
            float r00 = __fadd_rn(__fadd_rn(accS[mf][nf][0], accL[mf][nf][0]), b0);
            float r01 = __fadd_rn(__fadd_rn(accS[mf][nf][1], accL[mf][nf][1]), b0);
            float r10 = __fadd_rn(__fadd_rn(accS[mf][nf][2], accL[mf][nf][2]), b1);
            float r11 = __fadd_rn(__fadd_rn(accS[mf][nf][3], accL[mf][nf][3]), b1);
            *reinterpret_cast<float2*>(&Yb[(size_t)mrow * NN + ncol])       = make_float2(r00, r01);
            *reinterpret_cast<float2*>(&Yb[(size_t)(mrow + 8) * NN + ncol]) = make_float2(r10, r11);
        }
    }
}

// ---------------- fp32 -> 3-term bf16 split ---------------------------------
__global__ void split3_kernel(const float* __restrict__ in,
                              __nv_bfloat16* __restrict__ out,
                              size_t n, size_t stride)
{
    size_t i = (size_t)blockIdx.x * blockDim.x + threadIdx.x;
    if (i >= n) return;
    float v = in[i];
    __nv_bfloat16 h = __float2bfloat16(v);
    float r = __fsub_rn(v, __bfloat162float(h));
    __nv_bfloat16 m = __float2bfloat16(r);
    float r2 = __fsub_rn(r, __bfloat162float(m));
    __nv_bfloat16 l = __float2bfloat16(r2);
    out[i] = h; out[stride + i] = m; out[2 * stride + i] = l;
}

// ---------------- residual add + 3-term split (x2 = x + spikes) -------------
__global__ void addsplit_kernel(const float* __restrict__ x,
                                const __nv_bfloat16* __restrict__ s,
                                float* __restrict__ x2,
                                __nv_bfloat16* __restrict__ out, size_t n)
{
    size_t i = (size_t)blockIdx.x * blockDim.x + threadIdx.x;
    if (i >= n) return;
    float v = __fadd_rn(x[i], __bfloat162float(s[i]));
    x2[i] = v;
    __nv_bfloat16 h = __float2bfloat16(v);
    float r = __fsub_rn(v, __bfloat162float(h));
    __nv_bfloat16 m = __float2bfloat16(r);
    float r2 = __fsub_rn(r, __bfloat162float(m));
    out[i] = h; out[n + i] = m; out[2 * n + i] = __float2bfloat16(r2);
}

// ---------------- BatchNorm (exact reference forms) + LIF over T ------------
// Input y: [t*Bb+b][Mi][NN] rows [off, off+C). Output spikes: [t][b][C][N].
__global__ void bn_lif_kernel(const float* __restrict__ y,
                              __nv_bfloat16* __restrict__ out,
                              const float* __restrict__ bn,
                              int C, int Mi, int off, int useBN)
{
    const size_t plane = (size_t)Bb * C * NN;
    size_t idx = (size_t)blockIdx.x * blockDim.x + threadIdx.x;
    if (idx >= plane) return;
    int n = (int)(idx % NN);
    int c = (int)((idx / NN) % C);
    int b = (int)(idx / ((size_t)C * NN));

    float inv = 1.f, mu = 0.f, be = 0.f;
    if (useBN) {
        float g  = bn[c];
        be       = bn[C + c];
        mu       = bn[2 * C + c];
        float vr = bn[3 * C + c];
        inv = __fdiv_rn(g, __fsqrt_rn(__fadd_rn(vr, 1e-5f)));
    }

    const size_t inBase = ((size_t)b * Mi + off + c) * NN + n;
    const size_t inStep = (size_t)Bb * Mi * NN;

    float mem = 0.f;
#pragma unroll
    for (int t = 0; t < Tt; t++) {
        float v = y[inBase + (size_t)t * inStep];
        if (useBN)
            v = __fadd_rn(__fmul_rn(__fsub_rn(v, mu), inv), be);
        float d = __fsub_rn(v, mem);
        mem = __fadd_rn(mem, __fmul_rn(d, 0.5f));     // mem += (v-mem)/TAU
        float s = (mem > 0.5f) ? 1.f : 0.f;
        out[(size_t)t * plane + idx] = __float2bfloat16(s);
        mem = __fmul_rn(mem, __fsub_rn(1.f, s));      // hard reset
    }
}

// ---------------- attention (associative, no softmax), bf16 spikes in -------
// r = q @ (k^T v) * SCALE^2 — exact: integer counts * 0.0625.
__global__ void attn_kernel(const __nv_bfloat16* __restrict__ q,
                            const __nv_bfloat16* __restrict__ k,
                            const __nv_bfloat16* __restrict__ v,
                            float* __restrict__ r)
{
    __shared__ __nv_bfloat16 ks[DD][NN + 8];
    __shared__ __nv_bfloat16 vs[DD][NN + 8];
    __shared__ float S[DD][DD];

    const int blk = blockIdx.x;
    const int h   = blk % NHEADS;
    const int tb  = blk / NHEADS;
    const size_t base = (size_t)tb * CC * NN + (size_t)(h * DD) * NN;
    const int tid = threadIdx.x;   // 256

    for (int i = tid; i < DD * NN; i += 256) {
        int d = i >> 9;
        int n = i & (NN - 1);
        ks[d][n] = k[base + (size_t)d * NN + n];
        vs[d][n] = v[base + (size_t)d * NN + n];
    }
    __syncthreads();

    {   // S[d1][d2] = sum_m k[m,d1]*v[m,d2] (exact integer counts)
        int d1 = tid >> 4, d2 = tid & 15;
        float s = 0.f;
#pragma unroll 8
        for (int m = 0; m < NN; m++)
            s += __bfloat162float(ks[d1][m]) * __bfloat162float(vs[d2][m]);
        S[d1][d2] = s;
    }
    __syncthreads();

    for (int n = tid; n < NN; n += 256) {
        float qv[DD];
#pragma unroll
        for (int d1 = 0; d1 < DD; d1++)
            qv[d1] = __bfloat162float(q[base + (size_t)d1 * NN + n]);
#pragma unroll
        for (int d2 = 0; d2 < DD; d2++) {
            float acc = 0.f;
#pragma unroll
            for (int d1 = 0; d1 < DD; d1++) acc += qv[d1] * S[d1][d2];
            r[base + (size_t)d2 * NN + n] = acc * 0.0625f;  // SCALE*SCALE
        }
    }
}

// ---------------- final residual add ----------------------------------------
__global__ void final_add_kernel(const float* __restrict__ x2,
                                 const __nv_bfloat16* __restrict__ s,
                                 float* __restrict__ o, size_t n)
{
    size_t i = (size_t)blockIdx.x * blockDim.x + threadIdx.x;
    if (i >= n) return;
    o[i] = __fadd_rn(x2[i], __bfloat162float(s[i]));
}

// ---------------------------------------------------------------------------
extern "C" void kernel_launch(void* const* d_in, const int* in_sizes, int n_in,
                              void* d_out, int out_size)
{
    const float* x       = (const float*)d_in[0];
    const float* q_w     = (const float*)d_in[1];
    const float* q_bn    = (const float*)d_in[2];
    const float* k_w     = (const float*)d_in[3];
    const float* k_bn    = (const float*)d_in[4];
    const float* v_w     = (const float*)d_in[5];
    const float* v_bn    = (const float*)d_in[6];
    const float* proj_w  = (const float*)d_in[7];
    const float* proj_bn = (const float*)d_in[8];
    const float* fc1_w   = (const float*)d_in[9];
    const float* fc1_b   = (const float*)d_in[10];
    const float* fc1_bn  = (const float*)d_in[11];
    const float* fc2_w   = (const float*)d_in[12];
    const float* fc2_b   = (const float*)d_in[13];
    const float* fc2_bn  = (const float*)d_in[14];
    float* out = (float*)d_out;

    __nv_bfloat16 *wsp, *bsp, *gq, *gk, *gv, *gs, *gs2, *ghs;
    float *gf, *gh, *gx2;
    cudaGetSymbolAddress((void**)&wsp, g_wsplit);
    cudaGetSymbolAddress((void**)&bsp, g_bsplit);
    cudaGetSymbolAddress((void**)&gq,  g_q);
    cudaGetSymbolAddress((void**)&gk,  g_k);
    cudaGetSymbolAddress((void**)&gv,  g_v);
    cudaGetSymbolAddress((void**)&gs,  g_s);
    cudaGetSymbolAddress((void**)&gs2, g_s2);
    cudaGetSymbolAddress((void**)&ghs, g_hs);
    cudaGetSymbolAddress((void**)&gf,  g_f);
    cudaGetSymbolAddress((void**)&gh,  g_h);
    cudaGetSymbolAddress((void**)&gx2, g_x2);

    cudaFuncSetAttribute(gemm_mma, cudaFuncAttributeMaxDynamicSharedMemorySize,
                         SMEM_BYTES);

    const size_t planeC = (size_t)Bb * CC * NN;   // 2,097,152
    const size_t planeH = (size_t)Bb * HH * NN;   // 8,388,608
    const int gLifC = (int)((planeC + 255) / 256);
    const int gLifH = (int)((planeH + 255) / 256);
    const int gEltC = (int)((PLANE_C + 255) / 256);

    // weight splits: q/k/v interleaved into stacked [3][768][256]
    split3_kernel<<<256, 256>>>(q_w, wsp + OFF_QKV,          65536, 768*256);
    split3_kernel<<<256, 256>>>(k_w, wsp + OFF_QKV + 65536,  65536, 768*256);
    split3_kernel<<<256, 256>>>(v_w, wsp + OFF_QKV + 131072, 65536, 768*256);
    split3_kernel<<<256, 256>>>(proj_w, wsp + OFF_P,  65536, 65536);
    split3_kernel<<<1024, 256>>>(fc1_w, wsp + OFF_F1, 262144, 262144);
    split3_kernel<<<1024, 256>>>(fc2_w, wsp + OFF_F2, 262144, 262144);

    // x splits
    split3_kernel<<<gEltC, 256>>>(x, bsp, PLANE_C, PLANE_C);

    const dim3 gQKV(NN / 128, 768 / 128, NBATCH);   // (4, 6, 64)
    const dim3 gC  (NN / 128, CC / 128, NBATCH);    // (4, 2, 64)
    const dim3 gH  (NN / 128, HH / 128, NBATCH);    // (4, 8, 64)

    // stacked QKV: one fused split-GEMM -> per-tensor BN+LIF
    gemm_mma<<<gQKV, 256, SMEM_BYTES>>>(wsp + OFF_QKV, bsp, gh, nullptr, 768, CC, PLANE_C, 0);
    bn_lif_kernel<<<gLifC, 256>>>(gh, gq, q_bn, CC, 768, 0,   1);
    bn_lif_kernel<<<gLifC, 256>>>(gh, gk, k_bn, CC, 768, 256, 1);
    bn_lif_kernel<<<gLifC, 256>>>(gh, gv, v_bn, CC, 768, 512, 1);

    // attention (associative) + attn_lif
    attn_kernel<<<NBATCH * NHEADS, 256>>>(gq, gk, gv, gf);
    bn_lif_kernel<<<gLifC, 256>>>(gf, gs, nullptr, CC, CC, 0, 0);

    // proj (spike input: 3 exact combos) -> BN -> LIF, residual 1 + resplit
    gemm_mma<<<gC, 256, SMEM_BYTES>>>(wsp + OFF_P, gs, gf, nullptr, CC, CC, 0, 1);
    bn_lif_kernel<<<gLifC, 256>>>(gf, gs2, proj_bn, CC, CC, 0, 1);
    addsplit_kernel<<<gEltC, 256>>>(x, gs2, gx2, bsp, PLANE_C);

    // MLP
    gemm_mma<<<gH, 256, SMEM_BYTES>>>(wsp + OFF_F1, bsp, gh, fc1_b, HH, CC, PLANE_C, 0);
    bn_lif_kernel<<<gLifH, 256>>>(gh, ghs, fc1_bn, HH, HH, 0, 1);
    gemm_mma<<<gC, 256, SMEM_BYTES>>>(wsp + OFF_F2, ghs, gf, fc2_b, CC, HH, 0, 1);
    bn_lif_kernel<<<gLifC, 256>>>(gf, gs, fc2_bn, CC, CC, 0, 1);
    final_add_kernel<<<gEltC, 256>>>(gx2, gs, out, PLANE_C);
}